// round 15
// baseline (speedup 1.0000x reference)
#include <cuda_runtime.h>
#include <cstdint>

typedef unsigned long long u64;

#define B_  16
#define N_  8192
#define C_  256
#define K_  4096

// Output layout (float32): [features][indices][adjacency][scores]
#define OFF_FEAT   ((size_t)0)
#define OFF_IDX    ((size_t)B_ * K_ * C_)
#define OFF_ADJ    (OFF_IDX + (size_t)B_ * K_)
#define OFF_SCORES (OFF_ADJ + (size_t)B_ * K_ * K_)

// Scratch (device globals; no allocation allowed)
__device__ __align__(16) unsigned short g_idx[B_ * K_];
__device__ int g_pos[B_ * N_];
__device__ __align__(16) u64 g_keys[B_ * N_];      // 1 MB sort scratch
__device__ unsigned int g_arrive;                  // MONOTONIC barrier counter:
                                                   // each replay consumes one
                                                   // 128-arrival generation;
                                                   // never reset (replay-safe).

// Named barrier for the 256 sort threads (warps 0-7) only.
#define NB256() asm volatile("bar.sync 1, 256;" ::: "memory")

// ---------------------------------------------------------------------------
// Bitonic convention (chunk-local): lower element of a pair keeps the max iff
// (local_i & k)==0 => every chunk independently sorted DESCENDING.  Composite
// key flipped_score<<16 | (8191-idx) breaks ties by ascending index
// (jax.lax.top_k) and makes all keys unique => strict total order.
// ---------------------------------------------------------------------------
__device__ __forceinline__ void ce_pair(u64 &lo, u64 &hi, bool desc) {
    u64 a = lo, b = hi;
    u64 mx = a > b ? a : b;
    u64 mn = a > b ? b : a;
    lo = desc ? mx : mn;
    hi = desc ? mn : mx;
}
__device__ __forceinline__ u64 shfl_ce(u64 v, int j, bool keepmax) {
    u64 o = __shfl_xor_sync(0xFFFFFFFFu, v, j);
    u64 mx = v > o ? v : o;
    u64 mn = v > o ? o : v;
    return keepmax ? mx : mn;
}
__device__ __forceinline__ void smem_ce(u64* s, int i, int m, bool desc) {
    u64 a = s[i], c = s[m];
    if ((a < c) == desc) { s[i] = c; s[m] = a; }
}

// ---------------------------------------------------------------------------
// K1 (fused): Phase A — warps 0-7 sort this CTA's 1024-chunk descending
// (proven round-12 sort1024 body, syncs via named barrier so warps 8-15 can
// wait at the global barrier).  Device-wide monotonic barrier.  Phase B —
// all 512 threads rank the chunk's 1024 elements (2/thread, 14 interleaved
// binary searches => full MLP) and emit top-K results.
// grid B*8 = 128 CTAs (all resident: 128 < 148 SMs).
// ---------------------------------------------------------------------------
__global__ __launch_bounds__(512)
void sortrank_kernel(const float* __restrict__ scores,
                     float* __restrict__ out_idxf,
                     float* __restrict__ out_scores)
{
    __shared__ u64 s[1024];                          // 8 KB
    const int b     = blockIdx.x >> 3;
    const int chunk = blockIdx.x & 7;
    const int cb    = chunk << 10;                   // batch-local chunk base
    const int t     = threadIdx.x;

    // =================== Phase A: sort (threads 0-255) ===================
    if (t < 256) {
        const int l  = t & 31;
        const int wbase = (t >> 5) << 7;             // warp*128 (chunk-local)
        const float* sc = scores + (size_t)b * N_;

        u64 v[4];
        #pragma unroll
        for (int e = 0; e < 4; e++) {
            int I = cb + wbase + e * 32 + l;         // batch-local (for key)
            unsigned u = __float_as_uint(sc[I]);
            u ^= (u & 0x80000000u) ? 0xFFFFFFFFu : 0x80000000u;
            v[e] = ((u64)u << 16) | (unsigned)(8191 - I);
            g_pos[b * N_ + cb + e * 256 + t] = -1;
        }

        // ---- register phase: k = 2..128 ----
        #pragma unroll
        for (int k = 2; k <= 128; k <<= 1) {
            #pragma unroll
            for (int eb = 2; eb >= 1; eb >>= 1) {
                const int j = eb << 5;
                if (j < k) {
                    #pragma unroll
                    for (int e = 0; e < 4; e++)
                        if (!(e & eb)) {
                            bool desc = (((wbase + e * 32) & k) == 0);
                            ce_pair(v[e], v[e | eb], desc);
                        }
                }
            }
            #pragma unroll
            for (int j = 16; j >= 1; j >>= 1) {
                if (j < k) {
                    #pragma unroll
                    for (int e = 0; e < 4; e++) {
                        bool desc = (((wbase + e * 32 + l) & k) == 0);
                        v[e] = shfl_ce(v[e], j, desc == ((l & j) == 0));
                    }
                }
            }
        }

        // ---- k = 256, 512, 1024: smem stages j>=128, reg tail j<=64 ----
        #pragma unroll 1
        for (int k = 256; k <= 1024; k <<= 1) {
            #pragma unroll
            for (int e = 0; e < 4; e++) s[wbase + e * 32 + l] = v[e];
            NB256();
            #pragma unroll 1
            for (int j = k >> 1; j >= 128; j >>= 1) {
                #pragma unroll
                for (int q = 0; q < 2; q++) {
                    int p = t + q * 256;                   // 0..511 pairs
                    int i = ((p & ~(j - 1)) << 1) | (p & (j - 1));
                    bool desc = ((i & k) == 0);            // chunk-local
                    smem_ce(s, i, i + j, desc);
                }
                NB256();
            }
            #pragma unroll
            for (int e = 0; e < 4; e++) v[e] = s[wbase + e * 32 + l];
            NB256();
            #pragma unroll
            for (int eb = 2; eb >= 1; eb >>= 1) {
                #pragma unroll
                for (int e = 0; e < 4; e++)
                    if (!(e & eb)) {
                        bool desc = (((wbase + e * 32) & k) == 0);
                        ce_pair(v[e], v[e | eb], desc);
                    }
            }
            #pragma unroll
            for (int j = 16; j >= 1; j >>= 1) {
                #pragma unroll
                for (int e = 0; e < 4; e++) {
                    bool desc = (((wbase + e * 32 + l) & k) == 0);
                    v[e] = shfl_ce(v[e], j, desc == ((l & j) == 0));
                }
            }
        }

        // publish: smem (for phase B x-reads) + gmem (for other CTAs)
        #pragma unroll
        for (int e = 0; e < 4; e++) {
            s[wbase + e * 32 + l] = v[e];
            g_keys[(size_t)b * N_ + cb + wbase + e * 32 + l] = v[e];
        }
    }

    // =================== device-wide barrier (monotonic) ===================
    __threadfence();                        // release g_keys / g_pos writes
    __syncthreads();                        // all 512 (incl. idle warps 8-15)
    if (t == 0) {
        unsigned my  = atomicAdd(&g_arrive, 1u);
        unsigned tgt = ((my >> 7) + 1u) << 7;          // (gen+1)*128
        unsigned cur;
        do {
            asm volatile("ld.global.acquire.gpu.u32 %0, [%1];"
                         : "=r"(cur) : "l"(&g_arrive));
            if (cur >= tgt) break;
            __nanosleep(64);
        } while (true);
        __threadfence();
    }
    __syncthreads();

    // =================== Phase B: rank + emit (all 512) ===================
    const u64* keys = g_keys + (size_t)b * N_;
    const int p0 = t, p1 = t + 512;
    const u64 x0 = s[p0], x1 = s[p1];

    int lo0[8], hi0[8], lo1[8], hi1[8];
    #pragma unroll
    for (int c = 0; c < 8; c++) {
        lo0[c] = 0; hi0[c] = (c == chunk) ? 0 : 1024;
        lo1[c] = 0; hi1[c] = (c == chunk) ? 0 : 1024;
    }

    #pragma unroll
    for (int it = 0; it < 11; it++) {                  // ceil(log2(1025)) = 11
        #pragma unroll
        for (int c = 0; c < 8; c++) {
            if (lo0[c] < hi0[c]) {
                int mid = (lo0[c] + hi0[c]) >> 1;
                if (keys[(c << 10) + mid] > x0) lo0[c] = mid + 1; else hi0[c] = mid;
            }
            if (lo1[c] < hi1[c]) {
                int mid = (lo1[c] + hi1[c]) >> 1;
                if (keys[(c << 10) + mid] > x1) lo1[c] = mid + 1; else hi1[c] = mid;
            }
        }
    }

    int rank0 = p0, rank1 = p1;                        // own-chunk contribution
    #pragma unroll
    for (int c = 0; c < 8; c++) { rank0 += lo0[c]; rank1 += lo1[c]; }

    if (rank0 < K_) {
        int idx = 8191 - (int)(x0 & 0xFFFF);
        unsigned ku = (unsigned)(x0 >> 16);
        unsigned orig = (ku & 0x80000000u) ? (ku ^ 0x80000000u) : ~ku;
        g_idx[b * K_ + rank0] = (unsigned short)idx;
        out_idxf[(size_t)b * K_ + rank0]   = (float)idx;
        out_scores[(size_t)b * K_ + rank0] = __uint_as_float(orig);
        g_pos[b * N_ + idx] = rank0;
    }
    if (rank1 < K_) {
        int idx = 8191 - (int)(x1 & 0xFFFF);
        unsigned ku = (unsigned)(x1 >> 16);
        unsigned orig = (ku & 0x80000000u) ? (ku ^ 0x80000000u) : ~ku;
        g_idx[b * K_ + rank1] = (unsigned short)idx;
        out_idxf[(size_t)b * K_ + rank1]   = (float)idx;
        out_scores[(size_t)b * K_ + rank1] = __uint_as_float(orig);
        g_pos[b * N_ + idx] = rank1;
    }
}

// ---------------------------------------------------------------------------
// Combined gather — byte-identical to the proven round-14 best (264.0us).
// Static grid 10240, interleaved 4 adj : 1 feat unit mapping; bodies are the
// round-10 forms with streaming hints.
// ---------------------------------------------------------------------------
__global__ __launch_bounds__(512)
void gather_kernel(const float* __restrict__ A,
                   const float4* __restrict__ feat,
                   float* __restrict__ out_adj,
                   float4* __restrict__ out_feat)
{
    __shared__ float row[N_];   // 32 KB (adj branch only)
    const int v = blockIdx.x;
    const int g5 = v / 5;
    const int r5 = v - g5 * 5;

    if (r5 != 4) {
        const int r = g5 * 4 + r5;                      // 0..8191
        const float4* src  = (const float4*)(A + (size_t)r * N_);
        float4*       rowv = (float4*)row;
        for (int t = threadIdx.x; t < N_ / 4; t += 512)
            rowv[t] = __ldcs(src + t);
        __syncthreads();

        #pragma unroll 1
        for (int b = 0; b < B_; ++b) {
            int i = g_pos[b * N_ + r];
            if (i < 0) continue;
            float4* obase = (float4*)(out_adj + ((size_t)b * K_ + i) * K_);
            const ushort4* idx4 = (const ushort4*)(g_idx + b * K_);
            for (int t = threadIdx.x; t < K_ / 4; t += 512) {
                ushort4 c = idx4[t];
                __stcs(obase + t,
                       make_float4(row[c.x], row[c.y], row[c.z], row[c.w]));
            }
        }
    } else {
        const int q = g5;                               // 0..2047
        #pragma unroll
        for (int u = 0; u < 4; u++) {
            int o = (q * 4 + u) * 512 + threadIdx.x;    // 0..4194303
            int frow = o >> 6;                          // C/4=64 f4/row
            int c    = o & 63;
            int b    = frow >> 12;                      // K rows/batch
            int rr   = g_idx[frow];
            __stcs(out_feat + o,
                   __ldcs(feat + ((size_t)(b << 13) + rr) * 64 + c));
        }
    }
}

// ---------------------------------------------------------------------------
extern "C" void kernel_launch(void* const* d_in, const int* in_sizes, int n_in,
                              void* d_out, int out_size)
{
    const float* scores = (const float*)d_in[0];   // (B, N)
    const float* feat   = (const float*)d_in[1];   // (B, N, C)
    const float* adj    = (const float*)d_in[2];   // (N, N)
    float* out = (float*)d_out;

    float* out_feat   = out + OFF_FEAT;
    float* out_idxf   = out + OFF_IDX;
    float* out_adj    = out + OFF_ADJ;
    float* out_scores = out + OFF_SCORES;

    sortrank_kernel<<<B_ * 8, 512>>>(scores, out_idxf, out_scores);

    gather_kernel<<<10240, 512>>>(adj, (const float4*)feat,
                                  out_adj, (float4*)out_feat);
}

// round 16
// speedup vs baseline: 1.0113x; 1.0113x over previous
#include <cuda_runtime.h>
#include <cstdint>

typedef unsigned long long u64;

#define B_  16
#define N_  8192
#define C_  256
#define K_  4096

// Output layout (float32): [features][indices][adjacency][scores]
#define OFF_FEAT   ((size_t)0)
#define OFF_IDX    ((size_t)B_ * K_ * C_)
#define OFF_ADJ    (OFF_IDX + (size_t)B_ * K_)
#define OFF_SCORES (OFF_ADJ + (size_t)B_ * K_ * K_)

// Scratch (device globals; no allocation allowed)
__device__ __align__(16) unsigned short g_idx[B_ * K_];
__device__ int g_pos[B_ * N_];
__device__ __align__(16) u64 g_keys[B_ * N_];      // 1 MB sort scratch
__device__ unsigned int g_arrive;                  // MONOTONIC barrier counter
                                                   // (one 128-arrival generation
                                                   // per replay; never reset).

// Named barrier for the 256 sort threads (warps 0-7) only.
#define NB256() asm volatile("bar.sync 1, 256;" ::: "memory")

// ---------------------------------------------------------------------------
// Bitonic convention (chunk-local): lower element of a pair keeps the max iff
// (local_i & k)==0 => every chunk independently sorted DESCENDING.  Composite
// key flipped_score<<16 | (8191-idx) breaks ties by ascending index
// (jax.lax.top_k) and makes all keys unique => strict total order.
// ---------------------------------------------------------------------------
__device__ __forceinline__ void ce_pair(u64 &lo, u64 &hi, bool desc) {
    u64 a = lo, b = hi;
    u64 mx = a > b ? a : b;
    u64 mn = a > b ? b : a;
    lo = desc ? mx : mn;
    hi = desc ? mn : mx;
}
__device__ __forceinline__ u64 shfl_ce(u64 v, int j, bool keepmax) {
    u64 o = __shfl_xor_sync(0xFFFFFFFFu, v, j);
    u64 mx = v > o ? v : o;
    u64 mn = v > o ? o : v;
    return keepmax ? mx : mn;
}
__device__ __forceinline__ void smem_ce(u64* s, int i, int m, bool desc) {
    u64 a = s[i], c = s[m];
    if ((a < c) == desc) { s[i] = c; s[m] = a; }
}

// ---------------------------------------------------------------------------
// K1 (fused, PDL primary): Phase A — warps 0-7 sort this CTA's 1024-chunk
// descending; device-wide monotonic barrier; Phase B — all 512 threads rank
// the chunk (2 elems/thread, interleaved binary searches) and emit.
// Triggers programmatic launch of the gather at entry (correctness carried
// by the consumer's cudaGridDependencySynchronize).
// grid B*8 = 128 CTAs (all resident).
// ---------------------------------------------------------------------------
__global__ __launch_bounds__(512)
void sortrank_kernel(const float* __restrict__ scores,
                     float* __restrict__ out_idxf,
                     float* __restrict__ out_scores)
{
    cudaTriggerProgrammaticLaunchCompletion();       // let gather CTAs launch

    __shared__ u64 s[1024];                          // 8 KB
    const int b     = blockIdx.x >> 3;
    const int chunk = blockIdx.x & 7;
    const int cb    = chunk << 10;                   // batch-local chunk base
    const int t     = threadIdx.x;

    // =================== Phase A: sort (threads 0-255) ===================
    if (t < 256) {
        const int l  = t & 31;
        const int wbase = (t >> 5) << 7;             // warp*128 (chunk-local)
        const float* sc = scores + (size_t)b * N_;

        u64 v[4];
        #pragma unroll
        for (int e = 0; e < 4; e++) {
            int I = cb + wbase + e * 32 + l;         // batch-local (for key)
            unsigned u = __float_as_uint(sc[I]);
            u ^= (u & 0x80000000u) ? 0xFFFFFFFFu : 0x80000000u;
            v[e] = ((u64)u << 16) | (unsigned)(8191 - I);
            g_pos[b * N_ + cb + e * 256 + t] = -1;
        }

        // ---- register phase: k = 2..128 ----
        #pragma unroll
        for (int k = 2; k <= 128; k <<= 1) {
            #pragma unroll
            for (int eb = 2; eb >= 1; eb >>= 1) {
                const int j = eb << 5;
                if (j < k) {
                    #pragma unroll
                    for (int e = 0; e < 4; e++)
                        if (!(e & eb)) {
                            bool desc = (((wbase + e * 32) & k) == 0);
                            ce_pair(v[e], v[e | eb], desc);
                        }
                }
            }
            #pragma unroll
            for (int j = 16; j >= 1; j >>= 1) {
                if (j < k) {
                    #pragma unroll
                    for (int e = 0; e < 4; e++) {
                        bool desc = (((wbase + e * 32 + l) & k) == 0);
                        v[e] = shfl_ce(v[e], j, desc == ((l & j) == 0));
                    }
                }
            }
        }

        // ---- k = 256, 512, 1024: smem stages j>=128, reg tail j<=64 ----
        #pragma unroll 1
        for (int k = 256; k <= 1024; k <<= 1) {
            #pragma unroll
            for (int e = 0; e < 4; e++) s[wbase + e * 32 + l] = v[e];
            NB256();
            #pragma unroll 1
            for (int j = k >> 1; j >= 128; j >>= 1) {
                #pragma unroll
                for (int q = 0; q < 2; q++) {
                    int p = t + q * 256;                   // 0..511 pairs
                    int i = ((p & ~(j - 1)) << 1) | (p & (j - 1));
                    bool desc = ((i & k) == 0);            // chunk-local
                    smem_ce(s, i, i + j, desc);
                }
                NB256();
            }
            #pragma unroll
            for (int e = 0; e < 4; e++) v[e] = s[wbase + e * 32 + l];
            NB256();
            #pragma unroll
            for (int eb = 2; eb >= 1; eb >>= 1) {
                #pragma unroll
                for (int e = 0; e < 4; e++)
                    if (!(e & eb)) {
                        bool desc = (((wbase + e * 32) & k) == 0);
                        ce_pair(v[e], v[e | eb], desc);
                    }
            }
            #pragma unroll
            for (int j = 16; j >= 1; j >>= 1) {
                #pragma unroll
                for (int e = 0; e < 4; e++) {
                    bool desc = (((wbase + e * 32 + l) & k) == 0);
                    v[e] = shfl_ce(v[e], j, desc == ((l & j) == 0));
                }
            }
        }

        // publish: smem (for phase B x-reads) + gmem (for other CTAs)
        #pragma unroll
        for (int e = 0; e < 4; e++) {
            s[wbase + e * 32 + l] = v[e];
            g_keys[(size_t)b * N_ + cb + wbase + e * 32 + l] = v[e];
        }
    }

    // =================== device-wide barrier (monotonic) ===================
    __threadfence();                        // release g_keys / g_pos writes
    __syncthreads();                        // all 512 (incl. idle warps 8-15)
    if (t == 0) {
        unsigned my  = atomicAdd(&g_arrive, 1u);
        unsigned tgt = ((my >> 7) + 1u) << 7;          // (gen+1)*128
        unsigned cur;
        do {
            asm volatile("ld.global.acquire.gpu.u32 %0, [%1];"
                         : "=r"(cur) : "l"(&g_arrive));
            if (cur >= tgt) break;
            __nanosleep(64);
        } while (true);
        __threadfence();
    }
    __syncthreads();

    // =================== Phase B: rank + emit (all 512) ===================
    const u64* keys = g_keys + (size_t)b * N_;
    const int p0 = t, p1 = t + 512;
    const u64 x0 = s[p0], x1 = s[p1];

    int lo0[8], hi0[8], lo1[8], hi1[8];
    #pragma unroll
    for (int c = 0; c < 8; c++) {
        lo0[c] = 0; hi0[c] = (c == chunk) ? 0 : 1024;
        lo1[c] = 0; hi1[c] = (c == chunk) ? 0 : 1024;
    }

    #pragma unroll
    for (int it = 0; it < 11; it++) {                  // ceil(log2(1025)) = 11
        #pragma unroll
        for (int c = 0; c < 8; c++) {
            if (lo0[c] < hi0[c]) {
                int mid = (lo0[c] + hi0[c]) >> 1;
                if (keys[(c << 10) + mid] > x0) lo0[c] = mid + 1; else hi0[c] = mid;
            }
            if (lo1[c] < hi1[c]) {
                int mid = (lo1[c] + hi1[c]) >> 1;
                if (keys[(c << 10) + mid] > x1) lo1[c] = mid + 1; else hi1[c] = mid;
            }
        }
    }

    int rank0 = p0, rank1 = p1;                        // own-chunk contribution
    #pragma unroll
    for (int c = 0; c < 8; c++) { rank0 += lo0[c]; rank1 += lo1[c]; }

    if (rank0 < K_) {
        int idx = 8191 - (int)(x0 & 0xFFFF);
        unsigned ku = (unsigned)(x0 >> 16);
        unsigned orig = (ku & 0x80000000u) ? (ku ^ 0x80000000u) : ~ku;
        g_idx[b * K_ + rank0] = (unsigned short)idx;
        out_idxf[(size_t)b * K_ + rank0]   = (float)idx;
        out_scores[(size_t)b * K_ + rank0] = __uint_as_float(orig);
        g_pos[b * N_ + idx] = rank0;
    }
    if (rank1 < K_) {
        int idx = 8191 - (int)(x1 & 0xFFFF);
        unsigned ku = (unsigned)(x1 >> 16);
        unsigned orig = (ku & 0x80000000u) ? (ku ^ 0x80000000u) : ~ku;
        g_idx[b * K_ + rank1] = (unsigned short)idx;
        out_idxf[(size_t)b * K_ + rank1]   = (float)idx;
        out_scores[(size_t)b * K_ + rank1] = __uint_as_float(orig);
        g_pos[b * N_ + idx] = rank1;
    }
}

// ---------------------------------------------------------------------------
// K2 (PDL secondary): combined gather, bodies byte-identical to the proven
// round-14 best.  Pre-dependency phase stages the adjacency row (depends
// only on A); cudaGridDependencySynchronize() gates the g_pos/g_idx-
// dependent phase on sortrank grid completion.
// Static grid 10240, interleaved 4 adj : 1 feat unit mapping.
// ---------------------------------------------------------------------------
__global__ __launch_bounds__(512)
void gather_kernel(const float* __restrict__ A,
                   const float4* __restrict__ feat,
                   float* __restrict__ out_adj,
                   float4* __restrict__ out_feat)
{
    __shared__ float row[N_];   // 32 KB (adj branch only)
    const int v = blockIdx.x;
    const int g5 = v / 5;
    const int r5 = v - g5 * 5;

    if (r5 != 4) {
        const int r = g5 * 4 + r5;                      // 0..8191
        // ---- pre-dependency: stage source row (overlaps sortrank) ----
        const float4* src  = (const float4*)(A + (size_t)r * N_);
        float4*       rowv = (float4*)row;
        for (int t = threadIdx.x; t < N_ / 4; t += 512)
            rowv[t] = __ldcs(src + t);

        cudaGridDependencySynchronize();                // sortrank done
        __syncthreads();                                // row staged

        #pragma unroll 1
        for (int b = 0; b < B_; ++b) {
            int i = g_pos[b * N_ + r];
            if (i < 0) continue;
            float4* obase = (float4*)(out_adj + ((size_t)b * K_ + i) * K_);
            const ushort4* idx4 = (const ushort4*)(g_idx + b * K_);
            for (int t = threadIdx.x; t < K_ / 4; t += 512) {
                ushort4 c = idx4[t];
                __stcs(obase + t,
                       make_float4(row[c.x], row[c.y], row[c.z], row[c.w]));
            }
        }
    } else {
        cudaGridDependencySynchronize();                // needs g_idx

        const int q = g5;                               // 0..2047
        #pragma unroll
        for (int u = 0; u < 4; u++) {
            int o = (q * 4 + u) * 512 + threadIdx.x;    // 0..4194303
            int frow = o >> 6;                          // C/4=64 f4/row
            int c    = o & 63;
            int b    = frow >> 12;                      // K rows/batch
            int rr   = g_idx[frow];
            __stcs(out_feat + o,
                   __ldcs(feat + ((size_t)(b << 13) + rr) * 64 + c));
        }
    }
}

// ---------------------------------------------------------------------------
extern "C" void kernel_launch(void* const* d_in, const int* in_sizes, int n_in,
                              void* d_out, int out_size)
{
    const float* scores = (const float*)d_in[0];   // (B, N)
    const float* feat   = (const float*)d_in[1];   // (B, N, C)
    const float* adj    = (const float*)d_in[2];   // (N, N)
    float* out = (float*)d_out;

    float* out_feat   = out + OFF_FEAT;
    float* out_idxf   = out + OFF_IDX;
    float* out_adj    = out + OFF_ADJ;
    float* out_scores = out + OFF_SCORES;

    sortrank_kernel<<<B_ * 8, 512>>>(scores, out_idxf, out_scores);

    // Gather as PDL secondary: may launch while sortrank runs; its
    // griddepsync gates the dependent phase.
    cudaLaunchConfig_t cfg = {};
    cfg.gridDim  = dim3(10240);
    cfg.blockDim = dim3(512);
    cfg.dynamicSmemBytes = 0;
    cfg.stream = 0;                                   // same stream as above
    cudaLaunchAttribute attrs[1];
    attrs[0].id = cudaLaunchAttributeProgrammaticStreamSerialization;
    attrs[0].val.programmaticStreamSerializationAllowed = 1;
    cfg.attrs = attrs;
    cfg.numAttrs = 1;
    cudaLaunchKernelEx(&cfg, gather_kernel,
                       adj, (const float4*)feat, out_adj, (float4*)out_feat);
}

// round 17
// speedup vs baseline: 1.0417x; 1.0301x over previous
#include <cuda_runtime.h>
#include <cstdint>

typedef unsigned long long u64;

#define B_  16
#define N_  8192
#define C_  256
#define K_  4096

// Output layout (float32): [features][indices][adjacency][scores]
#define OFF_FEAT   ((size_t)0)
#define OFF_IDX    ((size_t)B_ * K_ * C_)
#define OFF_ADJ    (OFF_IDX + (size_t)B_ * K_)
#define OFF_SCORES (OFF_ADJ + (size_t)B_ * K_ * K_)

// Scratch (device globals; no allocation allowed)
__device__ __align__(16) unsigned short g_idx[B_ * K_];
__device__ int g_pos[B_ * N_];
__device__ __align__(16) u64 g_keys[B_ * N_];      // 1 MB sort scratch

// ---------------------------------------------------------------------------
// Bitonic convention (chunk-local): lower element of a pair keeps the max iff
// (local_i & k)==0 => every chunk independently sorted DESCENDING.  Composite
// key flipped_score<<16 | (8191-idx) breaks ties by ascending index
// (jax.lax.top_k) and makes all keys unique => strict total order.
// ---------------------------------------------------------------------------
__device__ __forceinline__ void ce_pair(u64 &lo, u64 &hi, bool desc) {
    u64 a = lo, b = hi;
    u64 mx = a > b ? a : b;
    u64 mn = a > b ? b : a;
    lo = desc ? mx : mn;
    hi = desc ? mn : mx;
}
__device__ __forceinline__ u64 shfl_ce(u64 v, int j, bool keepmax) {
    u64 o = __shfl_xor_sync(0xFFFFFFFFu, v, j);
    u64 mx = v > o ? v : o;
    u64 mn = v > o ? o : v;
    return keepmax ? mx : mn;
}
__device__ __forceinline__ void smem_ce(u64* s, int i, int m, bool desc) {
    u64 a = s[i], c = s[m];
    if ((a < c) == desc) { s[i] = c; s[m] = a; }
}

// ---------------------------------------------------------------------------
// K1: sort each 1024-chunk fully DESCENDING (proven round-12/14 body).
// grid B*8 = 128, block 256, 4 u64/thread, 8KB smem.  Triggers PDL at entry
// so rank_emit's CTAs pre-launch and park in griddepsync.
// ---------------------------------------------------------------------------
__global__ __launch_bounds__(256)
void sort1024_kernel(const float* __restrict__ scores)
{
    cudaTriggerProgrammaticLaunchCompletion();

    __shared__ u64 s[1024];
    const int b  = blockIdx.x >> 3;
    const int cb = (blockIdx.x & 7) << 10;          // batch-local chunk base
    const int t  = threadIdx.x;
    const int l  = t & 31;
    const int wbase = (t >> 5) << 7;                // warp*128 (chunk-local)
    const float* sc = scores + (size_t)b * N_;

    u64 v[4];
    #pragma unroll
    for (int e = 0; e < 4; e++) {
        int I = cb + wbase + e * 32 + l;            // batch-local (for key)
        unsigned u = __float_as_uint(sc[I]);
        u ^= (u & 0x80000000u) ? 0xFFFFFFFFu : 0x80000000u;
        v[e] = ((u64)u << 16) | (unsigned)(8191 - I);
        g_pos[b * N_ + cb + e * 256 + t] = -1;
    }

    // ---- register phase: k = 2..128 (chunk-local indices only) ----
    #pragma unroll
    for (int k = 2; k <= 128; k <<= 1) {
        #pragma unroll
        for (int eb = 2; eb >= 1; eb >>= 1) {
            const int j = eb << 5;
            if (j < k) {
                #pragma unroll
                for (int e = 0; e < 4; e++)
                    if (!(e & eb)) {
                        bool desc = (((wbase + e * 32) & k) == 0);
                        ce_pair(v[e], v[e | eb], desc);
                    }
            }
        }
        #pragma unroll
        for (int j = 16; j >= 1; j >>= 1) {
            if (j < k) {
                #pragma unroll
                for (int e = 0; e < 4; e++) {
                    bool desc = (((wbase + e * 32 + l) & k) == 0);
                    v[e] = shfl_ce(v[e], j, desc == ((l & j) == 0));
                }
            }
        }
    }

    // ---- k = 256, 512, 1024: smem stages j>=128, register tail j<=64 ----
    #pragma unroll 1
    for (int k = 256; k <= 1024; k <<= 1) {
        #pragma unroll
        for (int e = 0; e < 4; e++) s[wbase + e * 32 + l] = v[e];
        __syncthreads();
        #pragma unroll 1
        for (int j = k >> 1; j >= 128; j >>= 1) {
            #pragma unroll
            for (int q = 0; q < 2; q++) {
                int p = t + q * 256;                       // 0..511 pairs
                int i = ((p & ~(j - 1)) << 1) | (p & (j - 1));
                bool desc = ((i & k) == 0);                // chunk-local
                smem_ce(s, i, i + j, desc);
            }
            __syncthreads();
        }
        #pragma unroll
        for (int e = 0; e < 4; e++) v[e] = s[wbase + e * 32 + l];
        __syncthreads();
        #pragma unroll
        for (int eb = 2; eb >= 1; eb >>= 1) {
            #pragma unroll
            for (int e = 0; e < 4; e++)
                if (!(e & eb)) {
                    bool desc = (((wbase + e * 32) & k) == 0);
                    ce_pair(v[e], v[e | eb], desc);
                }
        }
        #pragma unroll
        for (int j = 16; j >= 1; j >>= 1) {
            #pragma unroll
            for (int e = 0; e < 4; e++) {
                bool desc = (((wbase + e * 32 + l) & k) == 0);
                v[e] = shfl_ce(v[e], j, desc == ((l & j) == 0));
            }
        }
    }

    #pragma unroll
    for (int e = 0; e < 4; e++)
        g_keys[(size_t)b * N_ + cb + wbase + e * 32 + l] = v[e];
}

// ---------------------------------------------------------------------------
// K2: merge-path rank + emit (proven round-14 body).  PDL secondary of
// sort1024: triggers its own completion at entry (so gather launches while
// sort1024 still runs), then griddepsyncs before touching g_keys.
// ---------------------------------------------------------------------------
__global__ __launch_bounds__(512)
void rank_emit_kernel(float* __restrict__ out_idxf,
                      float* __restrict__ out_scores)
{
    cudaTriggerProgrammaticLaunchCompletion();      // let gather pre-launch
    cudaGridDependencySynchronize();                // wait: sort1024 done

    const int gid = blockIdx.x * 512 + threadIdx.x;    // 0 .. B*N-1
    const int b = gid >> 13;
    const int i = gid & (N_ - 1);
    const u64* keys = g_keys + (size_t)b * N_;
    const u64 x = keys[i];
    const int chunk = i >> 10;

    int lo[8], hi[8];
    #pragma unroll
    for (int c = 0; c < 8; c++) {
        lo[c] = 0;
        hi[c] = (c == chunk) ? 0 : 1024;               // own chunk: no search
    }

    #pragma unroll
    for (int it = 0; it < 11; it++) {                  // ceil(log2(1025)) = 11
        #pragma unroll
        for (int c = 0; c < 8; c++) {
            if (lo[c] < hi[c]) {
                int mid = (lo[c] + hi[c]) >> 1;
                u64 val = keys[(c << 10) + mid];
                if (val > x) lo[c] = mid + 1; else hi[c] = mid;
            }
        }
    }

    int rank = i & 1023;                               // greater elems in own chunk
    #pragma unroll
    for (int c = 0; c < 8; c++) rank += lo[c];

    if (rank < K_) {
        int idx = 8191 - (int)(x & 0xFFFF);
        unsigned ku = (unsigned)(x >> 16);
        unsigned orig = (ku & 0x80000000u) ? (ku ^ 0x80000000u) : ~ku;
        g_idx[b * K_ + rank] = (unsigned short)idx;
        out_idxf[(size_t)b * K_ + rank]   = (float)idx;
        out_scores[(size_t)b * K_ + rank] = __uint_as_float(orig);
        g_pos[b * N_ + idx] = rank;
    }
}

// ---------------------------------------------------------------------------
// K3 (PDL secondary of rank_emit): combined gather, bodies byte-identical to
// the proven round-14 best.  Pre-dependency phase stages the adjacency row
// (reads only A) overlapping sort1024 + rank_emit; griddepsync gates the
// g_pos/g_idx-dependent phase.  Static grid 10240, 4 adj : 1 feat interleave.
// ---------------------------------------------------------------------------
__global__ __launch_bounds__(512)
void gather_kernel(const float* __restrict__ A,
                   const float4* __restrict__ feat,
                   float* __restrict__ out_adj,
                   float4* __restrict__ out_feat)
{
    __shared__ float row[N_];   // 32 KB (adj branch only)
    const int v = blockIdx.x;
    const int g5 = v / 5;
    const int r5 = v - g5 * 5;

    if (r5 != 4) {
        const int r = g5 * 4 + r5;                      // 0..8191
        // ---- pre-dependency: stage source row (overlaps sort + rank) ----
        const float4* src  = (const float4*)(A + (size_t)r * N_);
        float4*       rowv = (float4*)row;
        for (int t = threadIdx.x; t < N_ / 4; t += 512)
            rowv[t] = __ldcs(src + t);

        cudaGridDependencySynchronize();                // rank_emit done
        __syncthreads();                                // row staged

        #pragma unroll 1
        for (int b = 0; b < B_; ++b) {
            int i = g_pos[b * N_ + r];
            if (i < 0) continue;
            float4* obase = (float4*)(out_adj + ((size_t)b * K_ + i) * K_);
            const ushort4* idx4 = (const ushort4*)(g_idx + b * K_);
            for (int t = threadIdx.x; t < K_ / 4; t += 512) {
                ushort4 c = idx4[t];
                __stcs(obase + t,
                       make_float4(row[c.x], row[c.y], row[c.z], row[c.w]));
            }
        }
    } else {
        cudaGridDependencySynchronize();                // needs g_idx

        const int q = g5;                               // 0..2047
        #pragma unroll
        for (int u = 0; u < 4; u++) {
            int o = (q * 4 + u) * 512 + threadIdx.x;    // 0..4194303
            int frow = o >> 6;                          // C/4=64 f4/row
            int c    = o & 63;
            int b    = frow >> 12;                      // K rows/batch
            int rr   = g_idx[frow];
            __stcs(out_feat + o,
                   __ldcs(feat + ((size_t)(b << 13) + rr) * 64 + c));
        }
    }
}

// ---------------------------------------------------------------------------
extern "C" void kernel_launch(void* const* d_in, const int* in_sizes, int n_in,
                              void* d_out, int out_size)
{
    const float* scores = (const float*)d_in[0];   // (B, N)
    const float* feat   = (const float*)d_in[1];   // (B, N, C)
    const float* adj    = (const float*)d_in[2];   // (N, N)
    float* out = (float*)d_out;

    float* out_feat   = out + OFF_FEAT;
    float* out_idxf   = out + OFF_IDX;
    float* out_adj    = out + OFF_ADJ;
    float* out_scores = out + OFF_SCORES;

    // K1: plain launch (first in stream)
    sort1024_kernel<<<B_ * 8, 256>>>(scores);

    cudaLaunchAttribute attrs[1];
    attrs[0].id = cudaLaunchAttributeProgrammaticStreamSerialization;
    attrs[0].val.programmaticStreamSerializationAllowed = 1;

    // K2: PDL secondary of sort1024
    {
        cudaLaunchConfig_t cfg = {};
        cfg.gridDim  = dim3(B_ * N_ / 512);
        cfg.blockDim = dim3(512);
        cfg.stream   = 0;
        cfg.attrs    = attrs;
        cfg.numAttrs = 1;
        cudaLaunchKernelEx(&cfg, rank_emit_kernel, out_idxf, out_scores);
    }

    // K3: PDL secondary of rank_emit (pre-launches during sort via the
    // entry trigger in rank_emit)
    {
        cudaLaunchConfig_t cfg = {};
        cfg.gridDim  = dim3(10240);
        cfg.blockDim = dim3(512);
        cfg.stream   = 0;
        cfg.attrs    = attrs;
        cfg.numAttrs = 1;
        cudaLaunchKernelEx(&cfg, gather_kernel,
                           adj, (const float4*)feat, out_adj, (float4*)out_feat);
    }
}